// round 15
// baseline (speedup 1.0000x reference)
#include <cuda_runtime.h>
#include <cstdint>

// DepthEmissionRaymarcher: B=2,H=192,W=320,P=128,F=8
// R14: granule experiment. All prior rounds used __ldcs (evict-streaming) and
// measured exactly 3 full 128B lines/ray (48MB) despite only ~25MB of
// requested sectors — suspect streaming policy promotes DRAM fills to full
// lines. This round: default caching loads + R11's predicated feature pairs
// (pairs 1-3 loaded only while the group is unsaturated; prob==0 past
// saturation makes skipping bit-exact) + best-measured launch config
// (128-thread blocks). All shuffles warp-unconditional (divergence-safe).

static constexpr int P = 128;
static constexpr int F = 8;
static constexpr int WARPS_PER_BLOCK = 4;
static constexpr int THREADS = WARPS_PER_BLOCK * 32;
static constexpr int RAYS_PER_WARP = 8;

__global__ __launch_bounds__(THREADS)
void raymarch_kernel(const float* __restrict__ dens,
                     const float* __restrict__ feat,
                     const float* __restrict__ len,
                     float* __restrict__ depth_out,
                     float* __restrict__ feat_out,
                     int R)
{
    const unsigned FULL = 0xffffffffu;
    const int lane = threadIdx.x & 31;
    const int warp = threadIdx.x >> 5;
    const int g  = lane >> 2;        // ray-group within warp (0..7)
    const int sg = lane & 3;         // sub-lane: covers points 2sg, 2sg+1

    const int warp_ray0 = (blockIdx.x * WARPS_PER_BLOCK + warp) * RAYS_PER_WARP;
    if (warp_ray0 >= R) return;      // warp-uniform exit

    int ray = warp_ray0 + g;
    const bool valid = ray < R;
    if (!valid) ray = R - 1;         // safe addresses; writes predicated

    const float* draw = dens + (size_t)ray * P;
    const float* lraw = len  + (size_t)ray * P;
    const float* fraw = feat + (size_t)ray * P * F;

    float base = 0.0f;               // raw cumsum before current chunk
    float depth = 0.0f;
    float acc0 = 0.0f, acc1 = 0.0f;  // feature accum: indices 2sg, 2sg+1

    #pragma unroll 1
    for (int p0 = 0; p0 < P; p0 += 8) {
        const int pl = p0 + 2 * sg;  // this lane's first point

        // ---- front-batched loads (default caching, sector-granule fills) ----
        float2 d2 = *reinterpret_cast<const float2*>(draw + pl);
        float2 l2 = *reinterpret_cast<const float2*>(lraw + pl);
        // feature pair 0 (points p0, p0+1): probs always nonzero
        float2 f0 = *reinterpret_cast<const float2*>(fraw + (p0 + 0) * F + 2 * sg);
        float2 f1 = *reinterpret_cast<const float2*>(fraw + (p0 + 1) * F + 2 * sg);

        if (pl + 1 == P - 1) d2.y = 1.0f;   // wall=True on furthest sample

        // ---- scan: pair-sum then 2-round inclusive scan over 4 lanes ----
        const float s = d2.x + d2.y;
        float inc = s;
        {
            float v = __shfl_up_sync(FULL, inc, 1, 4);
            if (sg >= 1) inc += v;
            v = __shfl_up_sync(FULL, inc, 2, 4);
            if (sg >= 2) inc += v;
        }
        const float b    = base + (inc - s);      // cumsum before this lane's pts
        const float ckm1 = fminf(b, 1.0f);
        const float ck0  = fminf(b + d2.x, 1.0f);
        const float ck1  = fminf(b + s, 1.0f);
        const float pr0  = ck0 - ckm1;            // exactly 0 past saturation
        const float pr1  = ck1 - ck0;

        depth += pr0 * l2.x + pr1 * l2.y;

        // per-group saturation nibble; npairs = 1-based first saturated lane
        const unsigned mb = __ballot_sync(FULL, ck1 >= 1.0f);
        const unsigned gbits = (mb >> (g * 4)) & 0xFu;
        const int npairs = gbits ? (int)__ffs(gbits) : 4;

        // ---- feature pair 0: broadcast probs from lane 0 of group ----
        {
            const float pwa = __shfl_sync(FULL, pr0, 0, 4);
            const float pwb = __shfl_sync(FULL, pr1, 0, 4);
            acc0 += pwa * f0.x + pwb * f1.x;
            acc1 += pwa * f0.y + pwb * f1.y;
        }

        // ---- pairs 1..3: shfls unconditional (warp-converged); loads/FMAs
        // predicated per group so unneeded sectors are never requested ----
        #pragma unroll
        for (int i = 1; i < 4; i++) {
            const float pwa = __shfl_sync(FULL, pr0, i, 4);
            const float pwb = __shfl_sync(FULL, pr1, i, 4);
            if (i < npairs) {
                float2 fa = *reinterpret_cast<const float2*>(fraw + (p0 + 2 * i)     * F + 2 * sg);
                float2 fb = *reinterpret_cast<const float2*>(fraw + (p0 + 2 * i + 1) * F + 2 * sg);
                acc0 += pwa * fa.x + pwb * fb.x;
                acc1 += pwa * fa.y + pwb * fb.y;
            }
        }

        // ---- all groups saturated? (bit 4g+3 = lane3's ck1 = cumsum pt7) ----
        if ((mb & 0x88888888u) == 0x88888888u) break;

        base += __shfl_sync(FULL, inc, 3, 4);  // carry raw cumsum
    }

    // ---- depth: reduce over the 4 lanes of the group ----
    depth += __shfl_xor_sync(FULL, depth, 1);
    depth += __shfl_xor_sync(FULL, depth, 2);
    if (valid && sg == 0) depth_out[ray] = depth;

    // ---- features: lane stores feats {2sg, 2sg+1}; fully coalesced ----
    if (valid)
        *reinterpret_cast<float2*>(feat_out + (size_t)ray * F + 2 * sg) =
            make_float2(acc0, acc1);
}

extern "C" void kernel_launch(void* const* d_in, const int* in_sizes, int n_in,
                              void* d_out, int out_size)
{
    const float* dens = (const float*)d_in[0];  // (B,H,W,P,1)
    const float* feat = (const float*)d_in[1];  // (B,H,W,P,F)
    const float* len  = (const float*)d_in[2];  // (B,H,W,P)

    const int R = in_sizes[2] / P;              // number of rays

    float* depth_out = (float*)d_out;           // (B,H,W) flattened
    float* feat_out  = depth_out + R;           // (B,H,W,F) flattened

    const int rays_per_block = WARPS_PER_BLOCK * RAYS_PER_WARP;
    const int blocks = (R + rays_per_block - 1) / rays_per_block;
    raymarch_kernel<<<blocks, THREADS>>>(dens, feat, len, depth_out, feat_out, R);
}

// round 16
// speedup vs baseline: 1.0029x; 1.0029x over previous
#include <cuda_runtime.h>
#include <cstdint>

// DepthEmissionRaymarcher: B=2,H=192,W=320,P=128,F=8
// R15: converged-config kernel. Measured floor = DRAM row activations
// (~122K feature rows + ~60K dens/len rows ≈ 14µs kernel / ~10.3µs wall);
// every structural variant R11-R14 lands 10.3-11.0µs. This is R11 (best:
// predicated feature pairs, __ldcs, 128-thread blocks) with feature loads
// issued FIRST so the bottleneck stream's row activations queue earliest.
// 8 rays/warp, 4-lane groups, 2 pts/lane. Post-saturation probs are exactly
// 0 -> skipping is bit-exact. All shuffles warp-unconditional.

static constexpr int P = 128;
static constexpr int F = 8;
static constexpr int WARPS_PER_BLOCK = 4;
static constexpr int THREADS = WARPS_PER_BLOCK * 32;
static constexpr int RAYS_PER_WARP = 8;

__global__ __launch_bounds__(THREADS)
void raymarch_kernel(const float* __restrict__ dens,
                     const float* __restrict__ feat,
                     const float* __restrict__ len,
                     float* __restrict__ depth_out,
                     float* __restrict__ feat_out,
                     int R)
{
    const unsigned FULL = 0xffffffffu;
    const int lane = threadIdx.x & 31;
    const int warp = threadIdx.x >> 5;
    const int g  = lane >> 2;        // ray-group within warp (0..7)
    const int sg = lane & 3;         // sub-lane: covers points 2sg, 2sg+1

    const int warp_ray0 = (blockIdx.x * WARPS_PER_BLOCK + warp) * RAYS_PER_WARP;
    if (warp_ray0 >= R) return;      // warp-uniform exit

    int ray = warp_ray0 + g;
    const bool valid = ray < R;
    if (!valid) ray = R - 1;         // safe addresses; writes predicated

    const float* draw = dens + (size_t)ray * P;
    const float* lraw = len  + (size_t)ray * P;
    const float* fraw = feat + (size_t)ray * P * F;

    float base = 0.0f;               // raw cumsum before current chunk
    float depth = 0.0f;
    float acc0 = 0.0f, acc1 = 0.0f;  // feature accum: indices 2sg, 2sg+1

    #pragma unroll 1
    for (int p0 = 0; p0 < P; p0 += 8) {
        const int pl = p0 + 2 * sg;  // this lane's first point

        // ---- front-batched loads: FEATURES FIRST (activation-bound
        // stream), then dens/len (page-friendly 4-lines-per-row) ----
        float2 f0 = __ldcs(reinterpret_cast<const float2*>(fraw + (p0 + 0) * F + 2 * sg));
        float2 f1 = __ldcs(reinterpret_cast<const float2*>(fraw + (p0 + 1) * F + 2 * sg));
        float2 d2 = __ldcs(reinterpret_cast<const float2*>(draw + pl));
        float2 l2 = __ldcs(reinterpret_cast<const float2*>(lraw + pl));

        if (pl + 1 == P - 1) d2.y = 1.0f;   // wall=True on furthest sample

        // ---- scan: pair-sum then 2-round inclusive scan over 4 lanes ----
        const float s = d2.x + d2.y;
        float inc = s;
        {
            float v = __shfl_up_sync(FULL, inc, 1, 4);
            if (sg >= 1) inc += v;
            v = __shfl_up_sync(FULL, inc, 2, 4);
            if (sg >= 2) inc += v;
        }
        const float b    = base + (inc - s);      // cumsum before this lane's pts
        const float ckm1 = fminf(b, 1.0f);
        const float ck0  = fminf(b + d2.x, 1.0f);
        const float ck1  = fminf(b + s, 1.0f);
        const float pr0  = ck0 - ckm1;            // exactly 0 past saturation
        const float pr1  = ck1 - ck0;

        depth += pr0 * l2.x + pr1 * l2.y;

        // per-group saturation nibble; npairs = 1-based first saturated lane
        const unsigned mb = __ballot_sync(FULL, ck1 >= 1.0f);
        const unsigned gbits = (mb >> (g * 4)) & 0xFu;
        const int npairs = gbits ? (int)__ffs(gbits) : 4;

        // ---- feature pair 0: broadcast probs from lane 0 of group ----
        {
            const float pwa = __shfl_sync(FULL, pr0, 0, 4);
            const float pwb = __shfl_sync(FULL, pr1, 0, 4);
            acc0 += pwa * f0.x + pwb * f1.x;
            acc1 += pwa * f0.y + pwb * f1.y;
        }

        // ---- pairs 1..3: shfls unconditional (warp-converged); loads/FMAs
        // predicated per group so unneeded sectors are never requested ----
        #pragma unroll
        for (int i = 1; i < 4; i++) {
            const float pwa = __shfl_sync(FULL, pr0, i, 4);
            const float pwb = __shfl_sync(FULL, pr1, i, 4);
            if (i < npairs) {
                float2 fa = __ldcs(reinterpret_cast<const float2*>(fraw + (p0 + 2 * i)     * F + 2 * sg));
                float2 fb = __ldcs(reinterpret_cast<const float2*>(fraw + (p0 + 2 * i + 1) * F + 2 * sg));
                acc0 += pwa * fa.x + pwb * fb.x;
                acc1 += pwa * fa.y + pwb * fb.y;
            }
        }

        // ---- all groups saturated? (bit 4g+3 = lane3's ck1 = cumsum pt7) ----
        if ((mb & 0x88888888u) == 0x88888888u) break;

        base += __shfl_sync(FULL, inc, 3, 4);  // carry raw cumsum
    }

    // ---- depth: reduce over the 4 lanes of the group ----
    depth += __shfl_xor_sync(FULL, depth, 1);
    depth += __shfl_xor_sync(FULL, depth, 2);
    if (valid && sg == 0) depth_out[ray] = depth;

    // ---- features: lane stores feats {2sg, 2sg+1}; fully coalesced ----
    if (valid)
        *reinterpret_cast<float2*>(feat_out + (size_t)ray * F + 2 * sg) =
            make_float2(acc0, acc1);
}

extern "C" void kernel_launch(void* const* d_in, const int* in_sizes, int n_in,
                              void* d_out, int out_size)
{
    const float* dens = (const float*)d_in[0];  // (B,H,W,P,1)
    const float* feat = (const float*)d_in[1];  // (B,H,W,P,F)
    const float* len  = (const float*)d_in[2];  // (B,H,W,P)

    const int R = in_sizes[2] / P;              // number of rays

    float* depth_out = (float*)d_out;           // (B,H,W) flattened
    float* feat_out  = depth_out + R;           // (B,H,W,F) flattened

    const int rays_per_block = WARPS_PER_BLOCK * RAYS_PER_WARP;
    const int blocks = (R + rays_per_block - 1) / rays_per_block;
    raymarch_kernel<<<blocks, THREADS>>>(dens, feat, len, depth_out, feat_out, R);
}